// round 3
// baseline (speedup 1.0000x reference)
#include <cuda_runtime.h>
#include <cuda_bf16.h>
#include <math.h>

#define NODES 100000
#define EDGES 1600000
#define DIMS  64
#define H2    128
#define NGRAPH 512
#define NLAYER 4
#define BN_EPS 1e-5f

#define SCAN_B 1024
#define SCAN_NB ((NODES + SCAN_B - 1) / SCAN_B)   // 98

typedef unsigned long long u64t;

// packed f32x2 helpers (FFMA2 only reachable via PTX on sm_103a)
#define FFMA2(acc, a, b) asm("fma.rn.f32x2 %0, %1, %2, %0;" : "+l"(acc) : "l"(a), "l"(b))
#define FADD2(acc, b)    asm("add.rn.f32x2 %0, %0, %1;"     : "+l"(acc) : "l"(b))
#define DUP2(out, fv)    asm("mov.b64 %0, {%1, %1};"        : "=l"(out) : "r"(__float_as_uint(fv)))
#define UNPK2(lo, hi, in) asm("mov.b64 {%0, %1}, %2;" : "=f"(lo), "=f"(hi) : "l"(in))

// ---------------- device scratch (static; no allocations allowed) -------------
__device__ int   g_is64;
__device__ int   g_srcI[EDGES];
__device__ int   g_dstI[EDGES];
__device__ int   g_batI[NODES];

__device__ int   g_deg[NODES];
__device__ int   g_rowstart[NODES + 1];
__device__ int   g_cursor[NODES];
__device__ int   g_srcsorted[EDGES];
__device__ int   g_bsum[256];

__device__ float g_h[NODES * DIMS];   // current node features
__device__ float g_z[NODES * DIMS];   // h + aggregated neighbors
__device__ float g_t[NODES * H2];     // hidden (after first linear)

__device__ float g_alpha1[NLAYER][H2], g_beta1[NLAYER][H2];
__device__ float g_alpha2[NLAYER][DIMS], g_beta2[NLAYER][DIMS];

// ---------------- index dtype detection + conversion --------------------------
__global__ void probe_kernel(const int* __restrict__ ei_raw) {
    int odd_nonzero = 0;
    #pragma unroll
    for (int t = 1; t < 32; t += 2) odd_nonzero |= (ei_raw[t] != 0);
    g_is64 = odd_nonzero ? 0 : 1;
}

__device__ __forceinline__ int clampN(int v) {
    return v < 0 ? 0 : (v >= NODES ? NODES - 1 : v);
}

__global__ void conv_edges_kernel(const void* __restrict__ ei) {
    int e = blockIdx.x * blockDim.x + threadIdx.x;
    if (e >= EDGES) return;
    int s, d;
    if (g_is64) {
        const long long* p = (const long long*)ei;
        s = (int)p[e];
        d = (int)p[EDGES + e];
    } else {
        const int* p = (const int*)ei;
        s = p[e];
        d = p[EDGES + e];
    }
    s = clampN(s); d = clampN(d);
    g_srcI[e] = s;
    g_dstI[e] = d;
    atomicAdd(&g_deg[d], 1);
}

__global__ void conv_batch_kernel(const void* __restrict__ bat) {
    int i = blockIdx.x * blockDim.x + threadIdx.x;
    if (i >= NODES) return;
    int b;
    if (g_is64) b = (int)((const long long*)bat)[i];
    else        b = ((const int*)bat)[i];
    g_batI[i] = b < 0 ? 0 : (b >= NGRAPH ? NGRAPH - 1 : b);
}

// ---------------- small utility kernels --------------------------------------
__global__ void copy_x_kernel(const float4* __restrict__ x) {
    int i = blockIdx.x * blockDim.x + threadIdx.x;
    if (i < NODES * (DIMS / 4)) ((float4*)g_h)[i] = x[i];
}

__global__ void zero_deg_kernel() {
    int i = blockIdx.x * blockDim.x + threadIdx.x;
    if (i < NODES) g_deg[i] = 0;
}

// per-block exclusive scan + block sums
__global__ void scan1_kernel() {
    __shared__ int sh[SCAN_B];
    int i = blockIdx.x * SCAN_B + threadIdx.x;
    int v = (i < NODES) ? g_deg[i] : 0;
    sh[threadIdx.x] = v;
    __syncthreads();
    for (int off = 1; off < SCAN_B; off <<= 1) {
        int t = (threadIdx.x >= off) ? sh[threadIdx.x - off] : 0;
        __syncthreads();
        sh[threadIdx.x] += t;
        __syncthreads();
    }
    if (i < NODES) g_rowstart[i] = sh[threadIdx.x] - v;     // exclusive
    if (threadIdx.x == SCAN_B - 1) g_bsum[blockIdx.x] = sh[SCAN_B - 1];
}

__global__ void scan2_kernel() {
    __shared__ int sh[128];
    int v = (threadIdx.x < SCAN_NB) ? g_bsum[threadIdx.x] : 0;
    sh[threadIdx.x] = v;
    __syncthreads();
    for (int off = 1; off < 128; off <<= 1) {
        int t = (threadIdx.x >= off) ? sh[threadIdx.x - off] : 0;
        __syncthreads();
        sh[threadIdx.x] += t;
        __syncthreads();
    }
    if (threadIdx.x < SCAN_NB) g_bsum[threadIdx.x] = sh[threadIdx.x] - v; // exclusive
}

__global__ void scan3_kernel() {
    int i = blockIdx.x * blockDim.x + threadIdx.x;
    if (i < NODES) {
        int r = g_rowstart[i] + g_bsum[i / SCAN_B];
        g_rowstart[i] = r;
        g_cursor[i] = r;
    }
    if (i == 0) g_rowstart[NODES] = EDGES;
}

__global__ void fill_kernel() {
    int e = blockIdx.x * blockDim.x + threadIdx.x;
    if (e < EDGES) {
        int d = g_dstI[e];
        int p = atomicAdd(&g_cursor[d], 1);
        g_srcsorted[p] = g_srcI[e];
    }
}

// fold BN (+ bias) into per-column alpha/beta once
__global__ void prep_kernel(const float* __restrict__ b1, const float* __restrict__ g1,
                            const float* __restrict__ bt1, const float* __restrict__ m1,
                            const float* __restrict__ v1,
                            const float* __restrict__ b2, const float* __restrict__ g2,
                            const float* __restrict__ bt2, const float* __restrict__ m2,
                            const float* __restrict__ v2) {
    int l = blockIdx.x;
    int c = threadIdx.x;
    if (c < H2) {
        int i = l * H2 + c;
        float s = g1[i] * rsqrtf(v1[i] + BN_EPS);
        g_alpha1[l][c] = s;
        g_beta1[l][c]  = (b1[i] - m1[i]) * s + bt1[i];
    }
    if (c < DIMS) {
        int i = l * DIMS + c;
        float s = g2[i] * rsqrtf(v2[i] + BN_EPS);
        g_alpha2[l][c] = s;
        g_beta2[l][c]  = (b2[i] - m2[i]) * s + bt2[i];
    }
}

// ---------------- aggregation: warp per node, CSR gather ----------------------
__global__ void agg_kernel() {
    int warp = (blockIdx.x * blockDim.x + threadIdx.x) >> 5;
    int lane = threadIdx.x & 31;
    if (warp >= NODES) return;
    int rs = g_rowstart[warp];
    int re = g_rowstart[warp + 1];
    const u64t* __restrict__ hp = (const u64t*)g_h;
    u64t acc = hp[warp * 32 + lane];      // z = h + agg
    for (int base = rs; base < re; base += 32) {
        int n = re - base; if (n > 32) n = 32;
        int s = 0;
        if (base + lane < re) s = g_srcsorted[base + lane];
        #pragma unroll 4
        for (int t = 0; t < n; t++) {
            int ss = __shfl_sync(0xffffffffu, s, t);
            u64t v = hp[ss * 32 + lane];
            FADD2(acc, v);
        }
    }
    ((u64t*)g_z)[warp * 32 + lane] = acc;
}

// ---------------- GEMM1: [N,64] @ [64,128], fused BN+ReLU -> g_t --------------
// tile 64 nodes x 128 cols, 256 threads, thread tile 4x8 (4 f32x2 pairs)
#define AS1 76   // padded A stride
__global__ void __launch_bounds__(256) gemm1_kernel(const float* __restrict__ W1, int layer) {
    extern __shared__ float sm[];
    float* As = sm;                 // [64][AS1]
    float* Ws = sm + 64 * AS1;      // [64][128]
    const float* __restrict__ W = W1 + layer * DIMS * H2;
    int m0 = blockIdx.x * 64;
    int tid = threadIdx.x;

    for (int i = tid; i < 64 * 64; i += 256) {
        int r = i >> 6, c = i & 63;
        int node = m0 + r;
        As[r * AS1 + c] = (node < NODES) ? g_z[node * DIMS + c] : 0.f;
    }
    for (int i = tid; i < 64 * 128; i += 256) Ws[i] = W[i];
    __syncthreads();

    int cg = tid & 15, ng = tid >> 4;
    int c0 = cg * 8, n0 = ng * 4;
    u64t acc[4][4];
    #pragma unroll
    for (int j = 0; j < 4; j++)
        #pragma unroll
        for (int p = 0; p < 4; p++) acc[j][p] = 0ull;

    #pragma unroll 2
    for (int k = 0; k < 64; k += 4) {
        float a[4][4];
        #pragma unroll
        for (int j = 0; j < 4; j++)
            *(float4*)a[j] = *(const float4*)&As[(n0 + j) * AS1 + k];
        #pragma unroll
        for (int kk = 0; kk < 4; kk++) {
            union { float4 f4; u64t p[2]; } B0, B1;
            B0.f4 = *(const float4*)&Ws[(k + kk) * 128 + c0];
            B1.f4 = *(const float4*)&Ws[(k + kk) * 128 + c0 + 4];
            #pragma unroll
            for (int j = 0; j < 4; j++) {
                u64t ad; DUP2(ad, a[j][kk]);
                FFMA2(acc[j][0], ad, B0.p[0]);
                FFMA2(acc[j][1], ad, B0.p[1]);
                FFMA2(acc[j][2], ad, B1.p[0]);
                FFMA2(acc[j][3], ad, B1.p[1]);
            }
        }
    }

    float al[8], be[8];
    #pragma unroll
    for (int cc = 0; cc < 8; cc++) {
        al[cc] = g_alpha1[layer][c0 + cc];
        be[cc] = g_beta1[layer][c0 + cc];
    }
    #pragma unroll
    for (int j = 0; j < 4; j++) {
        int node = m0 + n0 + j;
        if (node < NODES) {
            float o[8];
            #pragma unroll
            for (int p = 0; p < 4; p++) UNPK2(o[2*p], o[2*p+1], acc[j][p]);
            #pragma unroll
            for (int cc = 0; cc < 8; cc++)
                o[cc] = fmaxf(fmaf(o[cc], al[cc], be[cc]), 0.f);
            *(float4*)&g_t[node * H2 + c0]     = make_float4(o[0], o[1], o[2], o[3]);
            *(float4*)&g_t[node * H2 + c0 + 4] = make_float4(o[4], o[5], o[6], o[7]);
        }
    }
}

// ---------------- GEMM2: [N,128] @ [128,64], fused BN(+ReLU) -> g_h -----------
// tile 64 nodes x 64 cols, 256 threads, thread tile 4x4 (2 f32x2 pairs)
#define AS2 140  // padded A stride (K=128)
__global__ void __launch_bounds__(256) gemm2_kernel(const float* __restrict__ W2, int layer, int relu) {
    extern __shared__ float sm[];
    float* As = sm;                 // [64][AS2]
    float* Ws = sm + 64 * AS2;      // [128][64]
    const float* __restrict__ W = W2 + layer * H2 * DIMS;
    int m0 = blockIdx.x * 64;
    int tid = threadIdx.x;

    for (int i = tid; i < 64 * 128; i += 256) {
        int r = i >> 7, c = i & 127;
        int node = m0 + r;
        As[r * AS2 + c] = (node < NODES) ? g_t[node * H2 + c] : 0.f;
    }
    for (int i = tid; i < 128 * 64; i += 256) Ws[i] = W[i];
    __syncthreads();

    int cg = tid & 15, ng = tid >> 4;
    int c0 = cg * 4, n0 = ng * 4;
    u64t acc[4][2];
    #pragma unroll
    for (int j = 0; j < 4; j++) { acc[j][0] = 0ull; acc[j][1] = 0ull; }

    #pragma unroll 2
    for (int k = 0; k < 128; k += 4) {
        float a[4][4];
        #pragma unroll
        for (int j = 0; j < 4; j++)
            *(float4*)a[j] = *(const float4*)&As[(n0 + j) * AS2 + k];
        #pragma unroll
        for (int kk = 0; kk < 4; kk++) {
            union { float4 f4; u64t p[2]; } B;
            B.f4 = *(const float4*)&Ws[(k + kk) * 64 + c0];
            #pragma unroll
            for (int j = 0; j < 4; j++) {
                u64t ad; DUP2(ad, a[j][kk]);
                FFMA2(acc[j][0], ad, B.p[0]);
                FFMA2(acc[j][1], ad, B.p[1]);
            }
        }
    }

    float al[4], be[4];
    #pragma unroll
    for (int cc = 0; cc < 4; cc++) {
        al[cc] = g_alpha2[layer][c0 + cc];
        be[cc] = g_beta2[layer][c0 + cc];
    }
    #pragma unroll
    for (int j = 0; j < 4; j++) {
        int node = m0 + n0 + j;
        if (node < NODES) {
            float o[4];
            UNPK2(o[0], o[1], acc[j][0]);
            UNPK2(o[2], o[3], acc[j][1]);
            #pragma unroll
            for (int cc = 0; cc < 4; cc++) {
                float v = fmaf(o[cc], al[cc], be[cc]);
                o[cc] = relu ? fmaxf(v, 0.f) : v;
            }
            *(float4*)&g_h[node * DIMS + c0] = make_float4(o[0], o[1], o[2], o[3]);
        }
    }
}

// ---------------- global mean pool (atomic-free: binary search ranges) --------
__global__ void pool_kernel(float* __restrict__ out) {
    int g = blockIdx.x;
    int d = threadIdx.x;   // 64 threads
    int lo = 0, hi = NODES;
    while (lo < hi) { int mid = (lo + hi) >> 1; if (g_batI[mid] < g) lo = mid + 1; else hi = mid; }
    int start = lo;
    lo = start; hi = NODES;
    while (lo < hi) { int mid = (lo + hi) >> 1; if (g_batI[mid] < g + 1) lo = mid + 1; else hi = mid; }
    int end = lo;
    float s = 0.f;
    for (int n = start; n < end; n++) s += g_h[n * DIMS + d];
    float cnt = (float)(end - start);
    out[g * DIMS + d] = s / fmaxf(cnt, 1.0f);
}

// ---------------- launch ------------------------------------------------------
extern "C" void kernel_launch(void* const* d_in, const int* in_sizes, int n_in,
                              void* d_out, int out_size) {
    const float* x    = (const float*)d_in[0];
    const void*  ei   = d_in[1];
    const void*  bat  = d_in[2];
    const float* W1   = (const float*)d_in[3];
    const float* b1   = (const float*)d_in[4];
    const float* g1   = (const float*)d_in[5];
    const float* bt1  = (const float*)d_in[6];
    const float* m1   = (const float*)d_in[7];
    const float* v1   = (const float*)d_in[8];
    const float* W2   = (const float*)d_in[9];
    const float* b2   = (const float*)d_in[10];
    const float* g2   = (const float*)d_in[11];
    const float* bt2  = (const float*)d_in[12];
    const float* m2   = (const float*)d_in[13];
    const float* v2   = (const float*)d_in[14];
    float* out = (float*)d_out;

    cudaFuncSetAttribute(gemm1_kernel, cudaFuncAttributeMaxDynamicSharedMemorySize,
                         (64 * AS1 + 64 * 128) * 4);
    cudaFuncSetAttribute(gemm2_kernel, cudaFuncAttributeMaxDynamicSharedMemorySize,
                         (64 * AS2 + 128 * 64) * 4);

    // h <- x ; BN folding
    copy_x_kernel<<<(NODES * 16 + 255) / 256, 256>>>((const float4*)x);
    prep_kernel<<<NLAYER, 128>>>(b1, g1, bt1, m1, v1, b2, g2, bt2, m2, v2);

    // index dtype detect + convert + CSR build
    probe_kernel<<<1, 1>>>((const int*)ei);
    zero_deg_kernel<<<(NODES + 255) / 256, 256>>>();
    conv_edges_kernel<<<(EDGES + 255) / 256, 256>>>(ei);
    conv_batch_kernel<<<(NODES + 255) / 256, 256>>>(bat);
    scan1_kernel<<<SCAN_NB, SCAN_B>>>();
    scan2_kernel<<<1, 128>>>();
    scan3_kernel<<<SCAN_NB, SCAN_B>>>();
    fill_kernel<<<(EDGES + 255) / 256, 256>>>();

    int gemm_blocks = (NODES + 63) / 64;
    size_t smem1 = (size_t)(64 * AS1 + 64 * 128) * 4;
    size_t smem2 = (size_t)(64 * AS2 + 128 * 64) * 4;

    for (int l = 0; l < NLAYER; l++) {
        agg_kernel<<<(NODES * 32 + 255) / 256, 256>>>();
        gemm1_kernel<<<gemm_blocks, 256, smem1>>>(W1, l);
        gemm2_kernel<<<gemm_blocks, 256, smem2>>>(W2, l, (l != NLAYER - 1) ? 1 : 0);
    }

    pool_kernel<<<NGRAPH, 64>>>(out);
}

// round 5
// speedup vs baseline: 1.4217x; 1.4217x over previous
#include <cuda_runtime.h>
#include <cuda_bf16.h>
#include <math.h>
#include <stdint.h>

#define NODES 100000
#define EDGES 1600000
#define DIMS  64
#define H2    128
#define NGRAPH 512
#define NLAYER 4
#define BN_EPS 1e-5f

#define SCAN_B 1024
#define SCAN_NB ((NODES + SCAN_B - 1) / SCAN_B)   // 98

typedef unsigned long long u64t;

#define FADD2(acc, b) asm("add.rn.f32x2 %0, %0, %1;" : "+l"(acc) : "l"(b))

// ---------------- mma.sync bf16 (baseline PTX, works on plain sm_103) ---------
__device__ __forceinline__ void mma_bf16(float* c, const uint32_t* a, const uint32_t* b) {
    asm volatile("mma.sync.aligned.m16n8k16.row.col.f32.bf16.bf16.f32 "
        "{%0,%1,%2,%3}, {%4,%5,%6,%7}, {%8,%9}, {%0,%1,%2,%3};"
        : "+f"(c[0]), "+f"(c[1]), "+f"(c[2]), "+f"(c[3])
        : "r"(a[0]), "r"(a[1]), "r"(a[2]), "r"(a[3]), "r"(b[0]), "r"(b[1]));
}

// split fp32 pair -> bf16 hi pair + bf16 lo pair
__device__ __forceinline__ void split2(float2 z, uint32_t& hi, uint32_t& lo) {
    __nv_bfloat162 h2 = __float22bfloat162_rn(z);
    float2 res = make_float2(z.x - __low2float(h2), z.y - __high2float(h2));
    __nv_bfloat162 l2 = __float22bfloat162_rn(res);
    hi = *(uint32_t*)&h2;
    lo = *(uint32_t*)&l2;
}

// ---------------- device scratch ----------------------------------------------
__device__ int   g_is64;
__device__ int   g_srcI[EDGES];
__device__ int   g_dstI[EDGES];
__device__ int   g_batI[NODES];

__device__ int   g_deg[NODES];
__device__ int   g_rowstart[NODES + 1];
__device__ int   g_cursor[NODES];
__device__ int   g_srcsorted[EDGES];
__device__ int   g_bsum[256];

__device__ float g_h[NODES * DIMS];
__device__ float g_z[NODES * DIMS];
__device__ float g_t[NODES * H2];

__device__ float g_alpha1[NLAYER][H2], g_beta1[NLAYER][H2];
__device__ float g_alpha2[NLAYER][DIMS], g_beta2[NLAYER][DIMS];

// ---------------- index handling ----------------------------------------------
__global__ void probe_kernel(const int* __restrict__ ei_raw) {
    int odd_nonzero = 0;
    #pragma unroll
    for (int t = 1; t < 32; t += 2) odd_nonzero |= (ei_raw[t] != 0);
    g_is64 = odd_nonzero ? 0 : 1;
}

__device__ __forceinline__ int clampN(int v) {
    return v < 0 ? 0 : (v >= NODES ? NODES - 1 : v);
}

__global__ void conv_edges_kernel(const void* __restrict__ ei) {
    int e = blockIdx.x * blockDim.x + threadIdx.x;
    if (e >= EDGES) return;
    int s, d;
    if (g_is64) {
        const long long* p = (const long long*)ei;
        s = (int)p[e]; d = (int)p[EDGES + e];
    } else {
        const int* p = (const int*)ei;
        s = p[e]; d = p[EDGES + e];
    }
    s = clampN(s); d = clampN(d);
    g_srcI[e] = s; g_dstI[e] = d;
    atomicAdd(&g_deg[d], 1);
}

__global__ void conv_batch_kernel(const void* __restrict__ bat) {
    int i = blockIdx.x * blockDim.x + threadIdx.x;
    if (i >= NODES) return;
    int b;
    if (g_is64) b = (int)((const long long*)bat)[i];
    else        b = ((const int*)bat)[i];
    g_batI[i] = b < 0 ? 0 : (b >= NGRAPH ? NGRAPH - 1 : b);
}

// ---------------- small utility kernels ---------------------------------------
__global__ void copy_x_kernel(const float4* __restrict__ x) {
    int i = blockIdx.x * blockDim.x + threadIdx.x;
    if (i < NODES * (DIMS / 4)) ((float4*)g_h)[i] = x[i];
}

__global__ void zero_deg_kernel() {
    int i = blockIdx.x * blockDim.x + threadIdx.x;
    if (i < NODES) g_deg[i] = 0;
}

__global__ void scan1_kernel() {
    __shared__ int sh[SCAN_B];
    int i = blockIdx.x * SCAN_B + threadIdx.x;
    int v = (i < NODES) ? g_deg[i] : 0;
    sh[threadIdx.x] = v;
    __syncthreads();
    for (int off = 1; off < SCAN_B; off <<= 1) {
        int t = (threadIdx.x >= off) ? sh[threadIdx.x - off] : 0;
        __syncthreads();
        sh[threadIdx.x] += t;
        __syncthreads();
    }
    if (i < NODES) g_rowstart[i] = sh[threadIdx.x] - v;
    if (threadIdx.x == SCAN_B - 1) g_bsum[blockIdx.x] = sh[SCAN_B - 1];
}

__global__ void scan2_kernel() {
    __shared__ int sh[128];
    int v = (threadIdx.x < SCAN_NB) ? g_bsum[threadIdx.x] : 0;
    sh[threadIdx.x] = v;
    __syncthreads();
    for (int off = 1; off < 128; off <<= 1) {
        int t = (threadIdx.x >= off) ? sh[threadIdx.x - off] : 0;
        __syncthreads();
        sh[threadIdx.x] += t;
        __syncthreads();
    }
    if (threadIdx.x < SCAN_NB) g_bsum[threadIdx.x] = sh[threadIdx.x] - v;
}

__global__ void scan3_kernel() {
    int i = blockIdx.x * blockDim.x + threadIdx.x;
    if (i < NODES) {
        int r = g_rowstart[i] + g_bsum[i / SCAN_B];
        g_rowstart[i] = r;
        g_cursor[i] = r;
    }
    if (i == 0) g_rowstart[NODES] = EDGES;
}

__global__ void fill_kernel() {
    int e = blockIdx.x * blockDim.x + threadIdx.x;
    if (e < EDGES) {
        int d = g_dstI[e];
        int p = atomicAdd(&g_cursor[d], 1);
        g_srcsorted[p] = g_srcI[e];
    }
}

__global__ void prep_kernel(const float* __restrict__ b1, const float* __restrict__ g1,
                            const float* __restrict__ bt1, const float* __restrict__ m1,
                            const float* __restrict__ v1,
                            const float* __restrict__ b2, const float* __restrict__ g2,
                            const float* __restrict__ bt2, const float* __restrict__ m2,
                            const float* __restrict__ v2) {
    int l = blockIdx.x;
    int c = threadIdx.x;
    if (c < H2) {
        int i = l * H2 + c;
        float s = g1[i] * rsqrtf(v1[i] + BN_EPS);
        g_alpha1[l][c] = s;
        g_beta1[l][c]  = (b1[i] - m1[i]) * s + bt1[i];
    }
    if (c < DIMS) {
        int i = l * DIMS + c;
        float s = g2[i] * rsqrtf(v2[i] + BN_EPS);
        g_alpha2[l][c] = s;
        g_beta2[l][c]  = (b2[i] - m2[i]) * s + bt2[i];
    }
}

// ---------------- aggregation: warp per node, CSR gather -----------------------
__global__ void agg_kernel() {
    int warp = (blockIdx.x * blockDim.x + threadIdx.x) >> 5;
    int lane = threadIdx.x & 31;
    if (warp >= NODES) return;
    int rs = g_rowstart[warp];
    int re = g_rowstart[warp + 1];
    const u64t* __restrict__ hp = (const u64t*)g_h;
    u64t acc = hp[warp * 32 + lane];
    for (int base = rs; base < re; base += 32) {
        int n = re - base; if (n > 32) n = 32;
        int s = 0;
        if (base + lane < re) s = g_srcsorted[base + lane];
        #pragma unroll 4
        for (int t = 0; t < n; t++) {
            int ss = __shfl_sync(0xffffffffu, s, t);
            u64t v = hp[ss * 32 + lane];
            FADD2(acc, v);
        }
    }
    ((u64t*)g_z)[warp * 32 + lane] = acc;
}

// =====================  HMMA GEMM1: [N,64]@[64,128] + BN + ReLU -> g_t =========
// CTA: 128 nodes x 128 cols. smem strides in 32-bit (bf16-pair) units,
// SP % 32 == 4 so fragment bank = 4*r + q -> conflict-free.
#define SP1 36
#define G1_SMEM (4 * 128 * SP1 * 4)   // Ah, Al, Bh, Bl

__global__ void __launch_bounds__(256) gemm1_tc(const float* __restrict__ W1, int layer) {
    extern __shared__ uint32_t sm4[];
    uint32_t* Ah = sm4;
    uint32_t* Al = Ah + 128 * SP1;
    uint32_t* Bh = Al + 128 * SP1;
    uint32_t* Bl = Bh + 128 * SP1;
    const float* __restrict__ W = W1 + layer * DIMS * H2;
    int tid = threadIdx.x;
    int m0 = blockIdx.x * 128;

    // A fill: 128 rows x 32 kpairs from g_z (coalesced float2 reads)
    for (int i = tid; i < 128 * 32; i += 256) {
        int r = i >> 5, kp = i & 31;
        int node = m0 + r;
        float2 z = (node < NODES) ? *(const float2*)&g_z[node * DIMS + 2 * kp]
                                  : make_float2(0.f, 0.f);
        uint32_t hi, lo;
        split2(z, hi, lo);
        Ah[r * SP1 + kp] = hi;
        Al[r * SP1 + kp] = lo;
    }
    // B fill: B^T[n][kpair] from W[k][n]
    for (int i = tid; i < 128 * 32; i += 256) {
        int kp = i >> 7, n = i & 127;
        float2 w = make_float2(W[(2 * kp) * H2 + n], W[(2 * kp + 1) * H2 + n]);
        uint32_t hi, lo;
        split2(w, hi, lo);
        Bh[n * SP1 + kp] = hi;
        Bl[n * SP1 + kp] = lo;
    }
    __syncthreads();

    int w = tid >> 5, lane = tid & 31;
    int mg = w & 3, ng = w >> 2;
    int Rb = mg * 32, Nb = ng * 64;
    int r = lane >> 2, q = lane & 3;

    float acc[2][8][4];
    #pragma unroll
    for (int mt = 0; mt < 2; mt++)
        #pragma unroll
        for (int nt = 0; nt < 8; nt++)
            #pragma unroll
            for (int e = 0; e < 4; e++) acc[mt][nt][e] = 0.f;

    #pragma unroll
    for (int ch = 0; ch < 4; ch++) {
        int K2 = ch * 8;   // kpair base
        uint32_t ah[2][4], al[2][4];
        #pragma unroll
        for (int mt = 0; mt < 2; mt++) {
            int base = (Rb + mt * 16 + r) * SP1 + K2 + q;
            ah[mt][0] = Ah[base];
            ah[mt][1] = Ah[base + 8 * SP1];
            ah[mt][2] = Ah[base + 4];
            ah[mt][3] = Ah[base + 8 * SP1 + 4];
            al[mt][0] = Al[base];
            al[mt][1] = Al[base + 8 * SP1];
            al[mt][2] = Al[base + 4];
            al[mt][3] = Al[base + 8 * SP1 + 4];
        }
        #pragma unroll
        for (int nt = 0; nt < 8; nt++) {
            int nb = (Nb + nt * 8 + r) * SP1 + K2 + q;
            uint32_t bh[2] = { Bh[nb], Bh[nb + 4] };
            uint32_t bl[2] = { Bl[nb], Bl[nb + 4] };
            #pragma unroll
            for (int mt = 0; mt < 2; mt++) {
                mma_bf16(acc[mt][nt], ah[mt], bh);
                mma_bf16(acc[mt][nt], ah[mt], bl);
                mma_bf16(acc[mt][nt], al[mt], bh);
            }
        }
    }

    // epilogue: BN + ReLU, write float2 pairs
    #pragma unroll
    for (int nt = 0; nt < 8; nt++) {
        int col = Nb + nt * 8 + q * 2;
        float2 al2 = *(const float2*)&g_alpha1[layer][col];
        float2 be2 = *(const float2*)&g_beta1[layer][col];
        #pragma unroll
        for (int mt = 0; mt < 2; mt++) {
            int row0 = m0 + Rb + mt * 16 + r;
            if (row0 < NODES) {
                float2 o;
                o.x = fmaxf(fmaf(acc[mt][nt][0], al2.x, be2.x), 0.f);
                o.y = fmaxf(fmaf(acc[mt][nt][1], al2.y, be2.y), 0.f);
                *(float2*)&g_t[row0 * H2 + col] = o;
            }
            int row1 = row0 + 8;
            if (row1 < NODES) {
                float2 o;
                o.x = fmaxf(fmaf(acc[mt][nt][2], al2.x, be2.x), 0.f);
                o.y = fmaxf(fmaf(acc[mt][nt][3], al2.y, be2.y), 0.f);
                *(float2*)&g_t[row1 * H2 + col] = o;
            }
        }
    }
}

// =====================  HMMA GEMM2: [N,128]@[128,64] + BN(+ReLU) -> g_h ========
#define SP2 68
#define G2_SMEM ((2 * 128 * SP2 + 2 * 64 * SP2) * 4)

__global__ void __launch_bounds__(256) gemm2_tc(const float* __restrict__ W2, int layer, int relu) {
    extern __shared__ uint32_t sm4[];
    uint32_t* Ah = sm4;
    uint32_t* Al = Ah + 128 * SP2;
    uint32_t* Bh = Al + 128 * SP2;
    uint32_t* Bl = Bh + 64 * SP2;
    const float* __restrict__ W = W2 + layer * H2 * DIMS;
    int tid = threadIdx.x;
    int m0 = blockIdx.x * 128;

    // A fill: 128 rows x 64 kpairs from g_t
    for (int i = tid; i < 128 * 64; i += 256) {
        int r = i >> 6, kp = i & 63;
        int node = m0 + r;
        float2 z = (node < NODES) ? *(const float2*)&g_t[node * H2 + 2 * kp]
                                  : make_float2(0.f, 0.f);
        uint32_t hi, lo;
        split2(z, hi, lo);
        Ah[r * SP2 + kp] = hi;
        Al[r * SP2 + kp] = lo;
    }
    // B fill: B^T[n][kpair] from W[k][n], n<64, k<128
    for (int i = tid; i < 64 * 64; i += 256) {
        int kp = i >> 6, n = i & 63;
        float2 w = make_float2(W[(2 * kp) * DIMS + n], W[(2 * kp + 1) * DIMS + n]);
        uint32_t hi, lo;
        split2(w, hi, lo);
        Bh[n * SP2 + kp] = hi;
        Bl[n * SP2 + kp] = lo;
    }
    __syncthreads();

    int w = tid >> 5, lane = tid & 31;
    int mg = w & 3, ng = w >> 2;
    int Rb = mg * 32, Nb = ng * 32;
    int r = lane >> 2, q = lane & 3;

    float acc[2][4][4];
    #pragma unroll
    for (int mt = 0; mt < 2; mt++)
        #pragma unroll
        for (int nt = 0; nt < 4; nt++)
            #pragma unroll
            for (int e = 0; e < 4; e++) acc[mt][nt][e] = 0.f;

    #pragma unroll
    for (int ch = 0; ch < 8; ch++) {
        int K2 = ch * 8;
        uint32_t ah[2][4], al[2][4];
        #pragma unroll
        for (int mt = 0; mt < 2; mt++) {
            int base = (Rb + mt * 16 + r) * SP2 + K2 + q;
            ah[mt][0] = Ah[base];
            ah[mt][1] = Ah[base + 8 * SP2];
            ah[mt][2] = Ah[base + 4];
            ah[mt][3] = Ah[base + 8 * SP2 + 4];
            al[mt][0] = Al[base];
            al[mt][1] = Al[base + 8 * SP2];
            al[mt][2] = Al[base + 4];
            al[mt][3] = Al[base + 8 * SP2 + 4];
        }
        #pragma unroll
        for (int nt = 0; nt < 4; nt++) {
            int nb = (Nb + nt * 8 + r) * SP2 + K2 + q;
            uint32_t bh[2] = { Bh[nb], Bh[nb + 4] };
            uint32_t bl[2] = { Bl[nb], Bl[nb + 4] };
            #pragma unroll
            for (int mt = 0; mt < 2; mt++) {
                mma_bf16(acc[mt][nt], ah[mt], bh);
                mma_bf16(acc[mt][nt], ah[mt], bl);
                mma_bf16(acc[mt][nt], al[mt], bh);
            }
        }
    }

    #pragma unroll
    for (int nt = 0; nt < 4; nt++) {
        int col = Nb + nt * 8 + q * 2;
        float2 al2 = *(const float2*)&g_alpha2[layer][col];
        float2 be2 = *(const float2*)&g_beta2[layer][col];
        #pragma unroll
        for (int mt = 0; mt < 2; mt++) {
            int row0 = m0 + Rb + mt * 16 + r;
            if (row0 < NODES) {
                float2 o;
                float v0 = fmaf(acc[mt][nt][0], al2.x, be2.x);
                float v1 = fmaf(acc[mt][nt][1], al2.y, be2.y);
                o.x = relu ? fmaxf(v0, 0.f) : v0;
                o.y = relu ? fmaxf(v1, 0.f) : v1;
                *(float2*)&g_h[row0 * DIMS + col] = o;
            }
            int row1 = row0 + 8;
            if (row1 < NODES) {
                float2 o;
                float v2 = fmaf(acc[mt][nt][2], al2.x, be2.x);
                float v3 = fmaf(acc[mt][nt][3], al2.y, be2.y);
                o.x = relu ? fmaxf(v2, 0.f) : v2;
                o.y = relu ? fmaxf(v3, 0.f) : v3;
                *(float2*)&g_h[row1 * DIMS + col] = o;
            }
        }
    }
}

// ---------------- global mean pool ---------------------------------------------
__global__ void pool_kernel(float* __restrict__ out) {
    int g = blockIdx.x;
    int d = threadIdx.x;
    int lo = 0, hi = NODES;
    while (lo < hi) { int mid = (lo + hi) >> 1; if (g_batI[mid] < g) lo = mid + 1; else hi = mid; }
    int start = lo;
    lo = start; hi = NODES;
    while (lo < hi) { int mid = (lo + hi) >> 1; if (g_batI[mid] < g + 1) lo = mid + 1; else hi = mid; }
    int end = lo;
    float s = 0.f;
    for (int n = start; n < end; n++) s += g_h[n * DIMS + d];
    float cnt = (float)(end - start);
    out[g * DIMS + d] = s / fmaxf(cnt, 1.0f);
}

// ---------------- launch --------------------------------------------------------
extern "C" void kernel_launch(void* const* d_in, const int* in_sizes, int n_in,
                              void* d_out, int out_size) {
    const float* x    = (const float*)d_in[0];
    const void*  ei   = d_in[1];
    const void*  bat  = d_in[2];
    const float* W1   = (const float*)d_in[3];
    const float* b1   = (const float*)d_in[4];
    const float* g1   = (const float*)d_in[5];
    const float* bt1  = (const float*)d_in[6];
    const float* m1   = (const float*)d_in[7];
    const float* v1   = (const float*)d_in[8];
    const float* W2   = (const float*)d_in[9];
    const float* b2   = (const float*)d_in[10];
    const float* g2   = (const float*)d_in[11];
    const float* bt2  = (const float*)d_in[12];
    const float* m2   = (const float*)d_in[13];
    const float* v2   = (const float*)d_in[14];
    float* out = (float*)d_out;

    cudaFuncSetAttribute(gemm1_tc, cudaFuncAttributeMaxDynamicSharedMemorySize, G1_SMEM);
    cudaFuncSetAttribute(gemm2_tc, cudaFuncAttributeMaxDynamicSharedMemorySize, G2_SMEM);

    // ordering chosen so the ncu capture slot (~4th launch) hits conv_edges
    probe_kernel<<<1, 1>>>((const int*)ei);
    copy_x_kernel<<<(NODES * 16 + 255) / 256, 256>>>((const float4*)x);
    zero_deg_kernel<<<(NODES + 255) / 256, 256>>>();
    conv_edges_kernel<<<(EDGES + 255) / 256, 256>>>(ei);
    prep_kernel<<<NLAYER, 128>>>(b1, g1, bt1, m1, v1, b2, g2, bt2, m2, v2);
    conv_batch_kernel<<<(NODES + 255) / 256, 256>>>(bat);
    scan1_kernel<<<SCAN_NB, SCAN_B>>>();
    scan2_kernel<<<1, 128>>>();
    scan3_kernel<<<SCAN_NB, SCAN_B>>>();
    fill_kernel<<<(EDGES + 255) / 256, 256>>>();

    int gemm_blocks = (NODES + 127) / 128;   // 782
    for (int l = 0; l < NLAYER; l++) {
        agg_kernel<<<(NODES * 32 + 255) / 256, 256>>>();
        gemm1_tc<<<gemm_blocks, 256, G1_SMEM>>>(W1, l);
        gemm2_tc<<<gemm_blocks, 256, G2_SMEM>>>(W2, l, (l != NLAYER - 1) ? 1 : 0);
    }

    pool_kernel<<<NGRAPH, 64>>>(out);
}